// round 14
// baseline (speedup 1.0000x reference)
#include <cuda_runtime.h>
#include <math.h>

// Problem constants
#define NN 512          // image size
#define NA 30           // angles
#define ND 729          // detectors
#define NL 3            // layers
#define NB 2            // batch
#define NC 32           // hidden channels

#define PI_F 3.14159265358979323846f

static const int BNN = NB * NN * NN;           // 524288
static const int BAD = NB * NA * ND;           // 43740
static const int NODD = 364;                   // number of odd taps 1..727

typedef unsigned long long ull;

// packed fp32x2 helpers (Blackwell packed-FP32; ptxas never auto-emits these)
#define FMA_F32X2(d, a, b, c) \
    asm("fma.rn.f32x2 %0, %1, %2, %3;" : "=l"(d) : "l"(a), "l"(b), "l"(c))
#define UNPACK_F32X2(lo, hi, in) \
    asm("mov.b64 {%0, %1}, %2;" : "=f"(lo), "=f"(hi) : "l"(in))

// ---------------- scratch (device globals; no allocation allowed) -----------
__device__ float g_X[NB * NN * NN];
__device__ float g_Z[NB * NN * NN];
__device__ float g_noise[NB * NN * NN];
__device__ float g_f0[NB * NC * NN * NN];
__device__ float g_f1[NB * NC * NN * NN];
__device__ float g_sp[NB * NA * ND];
__device__ float g_res[NB * NA * ND];

// ---------------- trivial copy ----------------------------------------------
__global__ void copy_kernel(float* __restrict__ dst, const float* __restrict__ src, int n) {
    int i = blockIdx.x * blockDim.x + threadIdx.x;
    if (i < n) dst[i] = src[i];
}

// ---------------- Radon forward ----------------------------------------------
__global__ void radon_kernel(const float* __restrict__ img,
                             const float* __restrict__ theta,
                             float* __restrict__ out) {
    int gw   = (int)((blockIdx.x * blockDim.x + threadIdx.x) >> 5);
    int lane = threadIdx.x & 31;
    if (gw >= BAD) return;
    int b   = gw / (NA * ND);
    int rem = gw - b * NA * ND;
    int a   = rem / ND;
    int s   = rem - a * ND;

    float th = theta[a];
    float cs = cosf(th), sn = sinf(th);
    float sv = (float)s - 364.0f;
    float base_r = sv * sn + 255.5f;
    float base_c = sv * cs + 255.5f;
    const float* im = img + b * NN * NN;

    float acc = 0.0f;
    for (int t = lane; t < ND; t += 32) {
        float tv = (float)t - 364.0f;
        float r = base_r + tv * cs;
        float c = base_c - tv * sn;
        float rf = floorf(r), cf = floorf(c);
        int r0 = (int)rf, c0 = (int)cf;
        float wr = r - rf, wc = c - cf;
        float v00 = 0.f, v01 = 0.f, v10 = 0.f, v11 = 0.f;
        bool r0k = (unsigned)r0 < (unsigned)NN;
        bool r1k = (unsigned)(r0 + 1) < (unsigned)NN;
        bool c0k = (unsigned)c0 < (unsigned)NN;
        bool c1k = (unsigned)(c0 + 1) < (unsigned)NN;
        if (r0k) {
            const float* rp = im + r0 * NN;
            if (c0k) v00 = rp[c0];
            if (c1k) v01 = rp[c0 + 1];
        }
        if (r1k) {
            const float* rp = im + (r0 + 1) * NN;
            if (c0k) v10 = rp[c0];
            if (c1k) v11 = rp[c0 + 1];
        }
        acc += (1.f - wr) * ((1.f - wc) * v00 + wc * v01)
             +        wr  * ((1.f - wc) * v10 + wc * v11);
    }
#pragma unroll
    for (int o = 16; o; o >>= 1) acc += __shfl_xor_sync(0xffffffffu, acc, o);
    if (lane == 0) out[gw] = acc;
}

// ---------------- Ramp filter (analytic time-domain equivalent) --------------
__global__ void filter_kernel(const float* __restrict__ sp,
                              const float* __restrict__ sino,
                              float* __restrict__ out, int mode) {
    __shared__ float row[ND];
    __shared__ float coef[NODD];
    int ba = blockIdx.x;                 // b*NA + a
    const float* r = sp + ba * ND;
    for (int i = threadIdx.x; i < ND; i += blockDim.x) row[i] = r[i];
    for (int i = threadIdx.x; i < NODD; i += blockDim.x) {
        float d = 2.0f * (float)i + 1.0f;
        coef[i] = -2.0f / (PI_F * PI_F * d * d);
    }
    __syncthreads();
    const float scale = PI_F / (2.0f * (float)NA);
    int m = blockIdx.y * blockDim.x + threadIdx.x;
    if (m >= ND) return;
    float g = 0.5f * row[m];
    for (int i = 0; i < NODD; i++) {
        int d = 2 * i + 1;
        float sum = 0.f;
        int lo = m - d; if (lo >= 0) sum += row[lo];
        int hi = m + d; if (hi < ND) sum += row[hi];
        g = fmaf(coef[i], sum, g);
    }
    float filtered = g * scale;
    out[ba * ND + m] = (mode == 0) ? (sino[ba * ND + m] - filtered) : filtered;
}

// ---------------- Backprojection (fused epilogue) -----------------------------
__global__ void backproj_kernel(const float* __restrict__ sino,
                                const float* __restrict__ theta,
                                const float* __restrict__ base,
                                const float* __restrict__ addl,
                                float* __restrict__ out,
                                const float* __restrict__ steps, int layer,
                                int mode) {
    __shared__ float cs_s[NA], sn_s[NA];
    if (threadIdx.x < NA) {
        float th = theta[threadIdx.x];
        cs_s[threadIdx.x] = cosf(th);
        sn_s[threadIdx.x] = sinf(th);
    }
    __syncthreads();
    int p = blockIdx.x * blockDim.x + threadIdx.x;
    if (p >= BNN) return;
    int b  = p / (NN * NN);
    int ij = p - b * NN * NN;
    int i  = ij / NN, j = ij - i * NN;
    float xi = (float)i - 255.5f;
    float xj = (float)j - 255.5f;
    const float* srow = sino + b * NA * ND;
    float acc = 0.0f;
#pragma unroll 5
    for (int a = 0; a < NA; a++) {
        float idx = cs_s[a] * xj + sn_s[a] * xi + 364.0f;
        float lof = floorf(idx);
        int lo = (int)lof;
        float w = idx - lof;
        float v = 0.f;
        if ((unsigned)lo < (unsigned)ND)       v += srow[a * ND + lo] * (1.0f - w);
        if ((unsigned)(lo + 1) < (unsigned)ND) v += srow[a * ND + lo + 1] * w;
        acc += v;
    }
    float step = steps[layer];
    float r;
    if (mode == 0) r = base[p] + step * acc;
    else           r = base[p] + addl[p] - step * acc;
    out[p] = r;
}

// ---------------- Conv 1 -> 32, ReLU -----------------------------------------
__global__ void conv1_kernel(const float* __restrict__ in,   // [B,N,N]
                             const float* __restrict__ w,    // [32,1,3,3]
                             const float* __restrict__ bias, // [32]
                             float* __restrict__ out) {      // [B,32,N,N]
    __shared__ float ws[32 * 9];
    __shared__ float bs[32];
    __shared__ float tile[10][35];
    int tid = threadIdx.x;
    for (int i = tid; i < 288; i += 256) ws[i] = w[i];
    if (tid < 32)  bs[tid] = bias[tid];
    int tx0 = blockIdx.x * 32, ty0 = blockIdx.y * 8, b = blockIdx.z;
    const float* ip = in + b * NN * NN;
    for (int i = tid; i < 340; i += 256) {
        int r = i / 34, c = i % 34;
        int gy = ty0 + r - 1, gx = tx0 + c - 1;
        tile[r][c] = ((unsigned)gy < (unsigned)NN && (unsigned)gx < (unsigned)NN)
                         ? ip[gy * NN + gx] : 0.f;
    }
    __syncthreads();
    int lx = tid & 31, ly = tid >> 5;
    float p[9];
#pragma unroll
    for (int ky = 0; ky < 3; ky++)
#pragma unroll
        for (int kx = 0; kx < 3; kx++) p[ky * 3 + kx] = tile[ly + ky][lx + kx];
    int gy = ty0 + ly, gx = tx0 + lx;
#pragma unroll
    for (int oc = 0; oc < 32; oc++) {
        float acc = bs[oc];
#pragma unroll
        for (int k = 0; k < 9; k++) acc = fmaf(ws[oc * 9 + k], p[k], acc);
        acc = fmaxf(acc, 0.f);
        out[((b * NC + oc) * NN + gy) * NN + gx] = acc;
    }
}

// ---------------- Conv 32 -> 32, ReLU ----------------------------------------
// f32x2 over ADJACENT OUTPUT CHANNELS, zero pack/unpack in the mainloop:
//  - weights transposed in smem to [c][tap][oc]: oc-pair = one aligned LDS.64
//  - input tile duplicated in smem as {v,v} float2: pre-broadcast pair per LDS.64
// Dyn smem: wt[9216] floats | bias[32] | dup tiles[32][10][35] float2 = 126592 B.
// 256 threads; warp w: oc-group (w&3)*8, row-half (w>>2)*4.
// lane: ly = half*4 + (lane&3), lx0 = (lane>>2)*4; per thread 4 px x 4 oc-pairs.
__global__ void __launch_bounds__(256, 1)
conv32_kernel(const float* __restrict__ in,   // [B,32,N,N]
              const float* __restrict__ w,    // [32,32,3,3]
              const float* __restrict__ bias, // [32]
              float* __restrict__ out) {      // [B,32,N,N]
    extern __shared__ float sm[];
    float* ws = sm;                            // 9216 floats, [ck][oc] ck=c*9+k
    float* bs = sm + 9216;                     // 32
    ull*   td = (ull*)(sm + 9216 + 32);        // 32*10*35 dup-pairs (89600 B)
    int tid = threadIdx.x;

    // transposed weight load: ws[ck*32 + oc] = w[oc*288 + ck]
    for (int j = tid; j < 9216; j += 256) {
        int ck = j >> 5, oc = j & 31;
        ws[j] = w[oc * 288 + ck];
    }
    if (tid < 32) bs[tid] = bias[tid];

    int tx0 = blockIdx.x * 32, ty0 = blockIdx.y * 8, b = blockIdx.z;
    const float* inb = in + b * NC * NN * NN;
    // duplicated halo tiles: td[(c*10+r)*35 + cc] = {v, v}
    for (int i = tid; i < 32 * 340; i += 256) {
        int c   = i / 340;
        int rem = i - c * 340;
        int r   = rem / 34;
        int cc  = rem - r * 34;
        int gy = ty0 + r - 1, gx = tx0 + cc - 1;
        float v = ((unsigned)gy < (unsigned)NN && (unsigned)gx < (unsigned)NN)
                      ? inb[c * NN * NN + gy * NN + gx] : 0.f;
        float2 vv = make_float2(v, v);
        ((float2*)td)[(c * 10 + r) * 35 + cc] = vv;
    }
    __syncthreads();

    int warp = tid >> 5, lane = tid & 31;
    int ocg  = warp & 3;               // oc base = ocg*8 (4 pairs)
    int half = warp >> 2;              // 0/1 -> rows 0-3 / 4-7
    int ly   = half * 4 + (lane & 3);
    int lx0  = (lane >> 2) * 4;        // 4 consecutive px

    ull acc[4][4];                     // [oc-pair][px]
#pragma unroll
    for (int o = 0; o < 4; o++)
#pragma unroll
        for (int q = 0; q < 4; q++) acc[o][q] = 0ULL;

    const ull* wpb = (const ull*)ws;   // pair index = ck*16 + ocp
    int ocp0 = ocg * 4;

#pragma unroll 1
    for (int c = 0; c < NC; c++) {
        const ull* tl = td + (c * 10) * 35;
        const ull* wc = wpb + c * 144 + ocp0;     // + k*16 + o
#pragma unroll
        for (int ky = 0; ky < 3; ky++) {
            const ull* rp = tl + (ly + ky) * 35 + lx0;
            ull v[6];
#pragma unroll
            for (int k = 0; k < 6; k++) v[k] = rp[k];
#pragma unroll
            for (int kx = 0; kx < 3; kx++) {
                const ull* wk = wc + (ky * 3 + kx) * 16;
#pragma unroll
                for (int o = 0; o < 4; o++) {
                    ull wp = wk[o];               // warp-uniform broadcast
                    FMA_F32X2(acc[o][0], wp, v[kx + 0], acc[o][0]);
                    FMA_F32X2(acc[o][1], wp, v[kx + 1], acc[o][1]);
                    FMA_F32X2(acc[o][2], wp, v[kx + 2], acc[o][2]);
                    FMA_F32X2(acc[o][3], wp, v[kx + 3], acc[o][3]);
                }
            }
        }
    }

    int gy = ty0 + ly;
#pragma unroll
    for (int o = 0; o < 4; o++) {
        int oc = ocg * 8 + 2 * o;
        float b0 = bs[oc], b1 = bs[oc + 1];
        float lo0, hi0, lo1, hi1, lo2, hi2, lo3, hi3;
        UNPACK_F32X2(lo0, hi0, acc[o][0]);
        UNPACK_F32X2(lo1, hi1, acc[o][1]);
        UNPACK_F32X2(lo2, hi2, acc[o][2]);
        UNPACK_F32X2(lo3, hi3, acc[o][3]);
        float4 r0 = make_float4(fmaxf(lo0 + b0, 0.f), fmaxf(lo1 + b0, 0.f),
                                fmaxf(lo2 + b0, 0.f), fmaxf(lo3 + b0, 0.f));
        float4 r1 = make_float4(fmaxf(hi0 + b1, 0.f), fmaxf(hi1 + b1, 0.f),
                                fmaxf(hi2 + b1, 0.f), fmaxf(hi3 + b1, 0.f));
        *(float4*)(out + ((b * NC + oc)     * NN + gy) * NN + tx0 + lx0) = r0;
        *(float4*)(out + ((b * NC + oc + 1) * NN + gy) * NN + tx0 + lx0) = r1;
    }
}

// ---------------- Conv 32 -> 1 (all channels resident, single sync) ----------
__global__ void conv4_kernel(const float* __restrict__ in,  // [B,32,N,N]
                             const float* __restrict__ w,   // [1,32,3,3]
                             float* __restrict__ out) {     // [B,N,N]
    __shared__ float ws[288];
    __shared__ float tiles[32 * 350];
    int tid = threadIdx.x;
    for (int i = tid; i < 288; i += 256) ws[i] = w[i];
    int tx0 = blockIdx.x * 32, ty0 = blockIdx.y * 8, b = blockIdx.z;
    const float* inb = in + b * NC * NN * NN;
    for (int i = tid; i < 32 * 340; i += 256) {
        int c   = i / 340;
        int rem = i - c * 340;
        int r   = rem / 34;
        int cc  = rem - r * 34;
        int gy = ty0 + r - 1, gx = tx0 + cc - 1;
        tiles[c * 350 + r * 35 + cc] =
            ((unsigned)gy < (unsigned)NN && (unsigned)gx < (unsigned)NN)
                ? inb[c * NN * NN + gy * NN + gx] : 0.f;
    }
    __syncthreads();
    int lx = tid & 31, ly = tid >> 5;
    float acc = 0.f;
    for (int c = 0; c < NC; c++) {
        const float* tl = tiles + c * 350;
#pragma unroll
        for (int ky = 0; ky < 3; ky++)
#pragma unroll
            for (int kx = 0; kx < 3; kx++)
                acc = fmaf(ws[c * 9 + ky * 3 + kx], tl[(ly + ky) * 35 + lx + kx], acc);
    }
    out[b * NN * NN + (ty0 + ly) * NN + tx0 + lx] = acc;
}

// ---------------- finalize: 3 copies of X -------------------------------------
__global__ void finalize_kernel(const float* __restrict__ X, float* __restrict__ out,
                                int out_size) {
    int i = blockIdx.x * blockDim.x + threadIdx.x;
    if (i < out_size) out[i] = X[i % BNN];
}

// ---------------- host orchestration ------------------------------------------
extern "C" void kernel_launch(void* const* d_in, const int* in_sizes, int n_in,
                              void* d_out, int out_size) {
    // input order: cond, x0, sinogram, theta, theta_label, w1,b1,w2,b2,w3,b3,w4,steps
    const float* x0    = (const float*)d_in[1];
    const float* sino  = (const float*)d_in[2];
    const float* theta = (const float*)d_in[3];
    const float* w1    = (const float*)d_in[5];
    const float* b1    = (const float*)d_in[6];
    const float* w2    = (const float*)d_in[7];
    const float* b2    = (const float*)d_in[8];
    const float* w3    = (const float*)d_in[9];
    const float* b3    = (const float*)d_in[10];
    const float* w4    = (const float*)d_in[11];
    const float* steps = (const float*)d_in[12];

    float *X, *Z, *noise, *f0, *f1, *sp, *res;
    cudaGetSymbolAddress((void**)&X,     g_X);
    cudaGetSymbolAddress((void**)&Z,     g_Z);
    cudaGetSymbolAddress((void**)&noise, g_noise);
    cudaGetSymbolAddress((void**)&f0,    g_f0);
    cudaGetSymbolAddress((void**)&f1,    g_f1);
    cudaGetSymbolAddress((void**)&sp,    g_sp);
    cudaGetSymbolAddress((void**)&res,   g_res);

    const int conv32_smem = (9216 + 32) * 4 + 32 * 10 * 35 * 8;   // 126592 B
    cudaFuncSetAttribute(conv32_kernel,
                         cudaFuncAttributeMaxDynamicSharedMemorySize, conv32_smem);

    const int radon_blocks = (BAD * 32 + 255) / 256;      // warp per output
    const dim3 conv_grid(NN / 32, NN / 8, NB);
    const dim3 filt_grid(NB * NA, 3);

    // X = x0
    copy_kernel<<<(BNN + 255) / 256, 256>>>(X, x0, BNN);

    for (int n = 0; n < NL; n++) {
        // data-consistency branch
        radon_kernel<<<radon_blocks, 256>>>(X, theta, sp);
        filter_kernel<<<filt_grid, 256>>>(sp, sino, res, /*mode=*/0);
        backproj_kernel<<<(BNN + 255) / 256, 256>>>(res, theta, X, nullptr, Z,
                                                    steps, n, /*mode=*/0);
        // denoiser branch
        conv1_kernel<<<conv_grid, 256>>>(X, w1 + n * 288, b1 + n * 32, f0);
        conv32_kernel<<<conv_grid, 256, conv32_smem>>>(f0, w2 + n * 9216, b2 + n * 32, f1);
        conv32_kernel<<<conv_grid, 256, conv32_smem>>>(f1, w3 + n * 9216, b3 + n * 32, f0);
        conv4_kernel<<<conv_grid, 256>>>(f0, w4 + n * 288, noise);

        radon_kernel<<<radon_blocks, 256>>>(noise, theta, sp);
        filter_kernel<<<filt_grid, 256>>>(sp, nullptr, res, /*mode=*/1);
        backproj_kernel<<<(BNN + 255) / 256, 256>>>(res, theta, Z, noise, X,
                                                    steps, n, /*mode=*/1);
    }

    finalize_kernel<<<(out_size + 255) / 256, 256>>>(X, (float*)d_out, out_size);
}

// round 15
// speedup vs baseline: 1.2904x; 1.2904x over previous
#include <cuda_runtime.h>
#include <math.h>

// Problem constants
#define NN 512          // image size
#define NA 30           // angles
#define ND 729          // detectors
#define NL 3            // layers
#define NB 2            // batch
#define NC 32           // hidden channels

#define PI_F 3.14159265358979323846f

static const int BNN = NB * NN * NN;           // 524288
static const int BAD = NB * NA * ND;           // 43740
static const int NODD = 364;                   // number of odd taps 1..727

typedef unsigned long long ull;

// packed fp32x2 helpers (Blackwell packed-FP32; ptxas never auto-emits these)
#define FMA_F32X2(d, a, b, c) \
    asm("fma.rn.f32x2 %0, %1, %2, %3;" : "=l"(d) : "l"(a), "l"(b), "l"(c))
#define UNPACK_F32X2(lo, hi, in) \
    asm("mov.b64 {%0, %1}, %2;" : "=f"(lo), "=f"(hi) : "l"(in))

// ---------------- scratch (device globals; no allocation allowed) -----------
__device__ float g_X[NB * NN * NN];
__device__ float g_Z[NB * NN * NN];
__device__ float g_noise[NB * NN * NN];
__device__ float g_f0[NB * NC * NN * NN];
__device__ float g_f1[NB * NC * NN * NN];
__device__ float g_sp[NB * NA * ND];
__device__ float g_res[NB * NA * ND];
__device__ float g_w2T[NL * 9216];    // transposed weights: [l][c*9+k][oc]
__device__ float g_w3T[NL * 9216];

// ---------------- trivial copy ----------------------------------------------
__global__ void copy_kernel(float* __restrict__ dst, const float* __restrict__ src, int n) {
    int i = blockIdx.x * blockDim.x + threadIdx.x;
    if (i < n) dst[i] = src[i];
}

// ---------------- weight transpose (one-time, coalesced writes) --------------
// in:  w[l][oc][c][3][3]  ->  out: wT[l][(c*9+k)*32 + oc]
__global__ void wtrans_kernel(const float* __restrict__ w2,
                              const float* __restrict__ w3,
                              float* __restrict__ w2T,
                              float* __restrict__ w3T) {
    int j = blockIdx.x * blockDim.x + threadIdx.x;
    if (j >= NL * 9216) return;
    int l = j / 9216, r = j - l * 9216;
    int ck = r >> 5, oc = r & 31;
    w2T[j] = w2[l * 9216 + oc * 288 + ck];
    w3T[j] = w3[l * 9216 + oc * 288 + ck];
}

// ---------------- Radon forward ----------------------------------------------
__global__ void radon_kernel(const float* __restrict__ img,
                             const float* __restrict__ theta,
                             float* __restrict__ out) {
    int gw   = (int)((blockIdx.x * blockDim.x + threadIdx.x) >> 5);
    int lane = threadIdx.x & 31;
    if (gw >= BAD) return;
    int b   = gw / (NA * ND);
    int rem = gw - b * NA * ND;
    int a   = rem / ND;
    int s   = rem - a * ND;

    float th = theta[a];
    float cs = cosf(th), sn = sinf(th);
    float sv = (float)s - 364.0f;
    float base_r = sv * sn + 255.5f;
    float base_c = sv * cs + 255.5f;
    const float* im = img + b * NN * NN;

    float acc = 0.0f;
    for (int t = lane; t < ND; t += 32) {
        float tv = (float)t - 364.0f;
        float r = base_r + tv * cs;
        float c = base_c - tv * sn;
        float rf = floorf(r), cf = floorf(c);
        int r0 = (int)rf, c0 = (int)cf;
        float wr = r - rf, wc = c - cf;
        float v00 = 0.f, v01 = 0.f, v10 = 0.f, v11 = 0.f;
        bool r0k = (unsigned)r0 < (unsigned)NN;
        bool r1k = (unsigned)(r0 + 1) < (unsigned)NN;
        bool c0k = (unsigned)c0 < (unsigned)NN;
        bool c1k = (unsigned)(c0 + 1) < (unsigned)NN;
        if (r0k) {
            const float* rp = im + r0 * NN;
            if (c0k) v00 = rp[c0];
            if (c1k) v01 = rp[c0 + 1];
        }
        if (r1k) {
            const float* rp = im + (r0 + 1) * NN;
            if (c0k) v10 = rp[c0];
            if (c1k) v11 = rp[c0 + 1];
        }
        acc += (1.f - wr) * ((1.f - wc) * v00 + wc * v01)
             +        wr  * ((1.f - wc) * v10 + wc * v11);
    }
#pragma unroll
    for (int o = 16; o; o >>= 1) acc += __shfl_xor_sync(0xffffffffu, acc, o);
    if (lane == 0) out[gw] = acc;
}

// ---------------- Ramp filter (analytic time-domain equivalent) --------------
__global__ void filter_kernel(const float* __restrict__ sp,
                              const float* __restrict__ sino,
                              float* __restrict__ out, int mode) {
    __shared__ float row[ND];
    __shared__ float coef[NODD];
    int ba = blockIdx.x;                 // b*NA + a
    const float* r = sp + ba * ND;
    for (int i = threadIdx.x; i < ND; i += blockDim.x) row[i] = r[i];
    for (int i = threadIdx.x; i < NODD; i += blockDim.x) {
        float d = 2.0f * (float)i + 1.0f;
        coef[i] = -2.0f / (PI_F * PI_F * d * d);
    }
    __syncthreads();
    const float scale = PI_F / (2.0f * (float)NA);
    int m = blockIdx.y * blockDim.x + threadIdx.x;
    if (m >= ND) return;
    float g = 0.5f * row[m];
    for (int i = 0; i < NODD; i++) {
        int d = 2 * i + 1;
        float sum = 0.f;
        int lo = m - d; if (lo >= 0) sum += row[lo];
        int hi = m + d; if (hi < ND) sum += row[hi];
        g = fmaf(coef[i], sum, g);
    }
    float filtered = g * scale;
    out[ba * ND + m] = (mode == 0) ? (sino[ba * ND + m] - filtered) : filtered;
}

// ---------------- Backprojection (fused epilogue) -----------------------------
__global__ void backproj_kernel(const float* __restrict__ sino,
                                const float* __restrict__ theta,
                                const float* __restrict__ base,
                                const float* __restrict__ addl,
                                float* __restrict__ out,
                                const float* __restrict__ steps, int layer,
                                int mode) {
    __shared__ float cs_s[NA], sn_s[NA];
    if (threadIdx.x < NA) {
        float th = theta[threadIdx.x];
        cs_s[threadIdx.x] = cosf(th);
        sn_s[threadIdx.x] = sinf(th);
    }
    __syncthreads();
    int p = blockIdx.x * blockDim.x + threadIdx.x;
    if (p >= BNN) return;
    int b  = p / (NN * NN);
    int ij = p - b * NN * NN;
    int i  = ij / NN, j = ij - i * NN;
    float xi = (float)i - 255.5f;
    float xj = (float)j - 255.5f;
    const float* srow = sino + b * NA * ND;
    float acc = 0.0f;
#pragma unroll 5
    for (int a = 0; a < NA; a++) {
        float idx = cs_s[a] * xj + sn_s[a] * xi + 364.0f;
        float lof = floorf(idx);
        int lo = (int)lof;
        float w = idx - lof;
        float v = 0.f;
        if ((unsigned)lo < (unsigned)ND)       v += srow[a * ND + lo] * (1.0f - w);
        if ((unsigned)(lo + 1) < (unsigned)ND) v += srow[a * ND + lo + 1] * w;
        acc += v;
    }
    float step = steps[layer];
    float r;
    if (mode == 0) r = base[p] + step * acc;
    else           r = base[p] + addl[p] - step * acc;
    out[p] = r;
}

// ---------------- Conv 1 -> 32, ReLU -----------------------------------------
__global__ void conv1_kernel(const float* __restrict__ in,   // [B,N,N]
                             const float* __restrict__ w,    // [32,1,3,3]
                             const float* __restrict__ bias, // [32]
                             float* __restrict__ out) {      // [B,32,N,N]
    __shared__ float ws[32 * 9];
    __shared__ float bs[32];
    __shared__ float tile[10][35];
    int tid = threadIdx.x;
    for (int i = tid; i < 288; i += 256) ws[i] = w[i];
    if (tid < 32)  bs[tid] = bias[tid];
    int tx0 = blockIdx.x * 32, ty0 = blockIdx.y * 8, b = blockIdx.z;
    const float* ip = in + b * NN * NN;
    for (int i = tid; i < 340; i += 256) {
        int r = i / 34, c = i % 34;
        int gy = ty0 + r - 1, gx = tx0 + c - 1;
        tile[r][c] = ((unsigned)gy < (unsigned)NN && (unsigned)gx < (unsigned)NN)
                         ? ip[gy * NN + gx] : 0.f;
    }
    __syncthreads();
    int lx = tid & 31, ly = tid >> 5;
    float p[9];
#pragma unroll
    for (int ky = 0; ky < 3; ky++)
#pragma unroll
        for (int kx = 0; kx < 3; kx++) p[ky * 3 + kx] = tile[ly + ky][lx + kx];
    int gy = ty0 + ly, gx = tx0 + lx;
#pragma unroll
    for (int oc = 0; oc < 32; oc++) {
        float acc = bs[oc];
#pragma unroll
        for (int k = 0; k < 9; k++) acc = fmaf(ws[oc * 9 + k], p[k], acc);
        acc = fmaxf(acc, 0.f);
        out[((b * NC + oc) * NN + gy) * NN + gx] = acc;
    }
}

// ---------------- Conv 32 -> 32, ReLU ----------------------------------------
// f32x2 over ADJACENT OUTPUT CHANNELS, zero pack/unpack in the mainloop:
//  - weights pre-transposed to [ck][oc] (coalesced smem fill); oc-pair = LDS.64
//  - input tiles duplicated in smem as {v,v}: pre-broadcast pair per LDS.64
//  - 16-channel phases: smem = 36864 + 128 + 44800 = 81792 B -> 2 blocks/SM
// 256 threads; warp w: oc-group (w&3)*8, row-half (w>>2)*4.
// lane: ly = half*4 + (lane&3), lx0 = (lane>>2)*4; per thread 4 px x 4 oc-pairs.
__global__ void __launch_bounds__(256, 2)
conv32_kernel(const float* __restrict__ in,   // [B,32,N,N]
              const float* __restrict__ wT,   // [288][32] pre-transposed
              const float* __restrict__ bias, // [32]
              float* __restrict__ out) {      // [B,32,N,N]
    extern __shared__ float sm[];
    float* ws = sm;                            // 9216 floats [ck*32 + oc]
    float* bs = sm + 9216;                     // 32
    ull*   td = (ull*)(sm + 9216 + 32);        // 16*10*35 dup-pairs (44800 B)
    int tid = threadIdx.x;

    for (int i = tid; i < 9216; i += 256) ws[i] = wT[i];   // coalesced
    if (tid < 32) bs[tid] = bias[tid];

    int tx0 = blockIdx.x * 32, ty0 = blockIdx.y * 8, b = blockIdx.z;
    const float* inb = in + b * NC * NN * NN;

    int warp = tid >> 5, lane = tid & 31;
    int ocg  = warp & 3;               // oc base = ocg*8 (4 pairs)
    int half = warp >> 2;              // 0/1 -> rows 0-3 / 4-7
    int ly   = half * 4 + (lane & 3);
    int lx0  = (lane >> 2) * 4;        // 4 consecutive px

    ull acc[4][4];                     // [oc-pair][px]
#pragma unroll
    for (int o = 0; o < 4; o++)
#pragma unroll
        for (int q = 0; q < 4; q++) acc[o][q] = 0ULL;

    const ull* wpb = (const ull*)ws;   // pair index = ck*16 + ocp
    int ocp0 = ocg * 4;

#pragma unroll 1
    for (int ph = 0; ph < 2; ph++) {
        __syncthreads();
        // load 16 duplicated halo tiles for channels ph*16 .. ph*16+15
        for (int i = tid; i < 16 * 340; i += 256) {
            int c   = i / 340;
            int rem = i - c * 340;
            int r   = rem / 34;
            int cc  = rem - r * 34;
            int gy = ty0 + r - 1, gx = tx0 + cc - 1;
            float v = ((unsigned)gy < (unsigned)NN && (unsigned)gx < (unsigned)NN)
                          ? inb[(ph * 16 + c) * NN * NN + gy * NN + gx] : 0.f;
            ((float2*)td)[(c * 10 + r) * 35 + cc] = make_float2(v, v);
        }
        __syncthreads();

#pragma unroll 1
        for (int c = 0; c < 16; c++) {
            const ull* tl = td + (c * 10) * 35;
            const ull* wc = wpb + (ph * 16 + c) * 144 + ocp0;   // + k*16 + o
#pragma unroll
            for (int ky = 0; ky < 3; ky++) {
                const ull* rp = tl + (ly + ky) * 35 + lx0;
                ull v[6];
#pragma unroll
                for (int k = 0; k < 6; k++) v[k] = rp[k];
#pragma unroll
                for (int kx = 0; kx < 3; kx++) {
                    const ull* wk = wc + (ky * 3 + kx) * 16;
#pragma unroll
                    for (int o = 0; o < 4; o++) {
                        ull wp = wk[o];           // warp-uniform broadcast
                        FMA_F32X2(acc[o][0], wp, v[kx + 0], acc[o][0]);
                        FMA_F32X2(acc[o][1], wp, v[kx + 1], acc[o][1]);
                        FMA_F32X2(acc[o][2], wp, v[kx + 2], acc[o][2]);
                        FMA_F32X2(acc[o][3], wp, v[kx + 3], acc[o][3]);
                    }
                }
            }
        }
    }

    int gy = ty0 + ly;
#pragma unroll
    for (int o = 0; o < 4; o++) {
        int oc = ocg * 8 + 2 * o;
        float b0 = bs[oc], b1 = bs[oc + 1];
        float lo0, hi0, lo1, hi1, lo2, hi2, lo3, hi3;
        UNPACK_F32X2(lo0, hi0, acc[o][0]);
        UNPACK_F32X2(lo1, hi1, acc[o][1]);
        UNPACK_F32X2(lo2, hi2, acc[o][2]);
        UNPACK_F32X2(lo3, hi3, acc[o][3]);
        float4 r0 = make_float4(fmaxf(lo0 + b0, 0.f), fmaxf(lo1 + b0, 0.f),
                                fmaxf(lo2 + b0, 0.f), fmaxf(lo3 + b0, 0.f));
        float4 r1 = make_float4(fmaxf(hi0 + b1, 0.f), fmaxf(hi1 + b1, 0.f),
                                fmaxf(hi2 + b1, 0.f), fmaxf(hi3 + b1, 0.f));
        *(float4*)(out + ((b * NC + oc)     * NN + gy) * NN + tx0 + lx0) = r0;
        *(float4*)(out + ((b * NC + oc + 1) * NN + gy) * NN + tx0 + lx0) = r1;
    }
}

// ---------------- Conv 32 -> 1 (all channels resident, single sync) ----------
__global__ void conv4_kernel(const float* __restrict__ in,  // [B,32,N,N]
                             const float* __restrict__ w,   // [1,32,3,3]
                             float* __restrict__ out) {     // [B,N,N]
    __shared__ float ws[288];
    __shared__ float tiles[32 * 350];
    int tid = threadIdx.x;
    for (int i = tid; i < 288; i += 256) ws[i] = w[i];
    int tx0 = blockIdx.x * 32, ty0 = blockIdx.y * 8, b = blockIdx.z;
    const float* inb = in + b * NC * NN * NN;
    for (int i = tid; i < 32 * 340; i += 256) {
        int c   = i / 340;
        int rem = i - c * 340;
        int r   = rem / 34;
        int cc  = rem - r * 34;
        int gy = ty0 + r - 1, gx = tx0 + cc - 1;
        tiles[c * 350 + r * 35 + cc] =
            ((unsigned)gy < (unsigned)NN && (unsigned)gx < (unsigned)NN)
                ? inb[c * NN * NN + gy * NN + gx] : 0.f;
    }
    __syncthreads();
    int lx = tid & 31, ly = tid >> 5;
    float acc = 0.f;
    for (int c = 0; c < NC; c++) {
        const float* tl = tiles + c * 350;
#pragma unroll
        for (int ky = 0; ky < 3; ky++)
#pragma unroll
            for (int kx = 0; kx < 3; kx++)
                acc = fmaf(ws[c * 9 + ky * 3 + kx], tl[(ly + ky) * 35 + lx + kx], acc);
    }
    out[b * NN * NN + (ty0 + ly) * NN + tx0 + lx] = acc;
}

// ---------------- finalize: 3 copies of X -------------------------------------
__global__ void finalize_kernel(const float* __restrict__ X, float* __restrict__ out,
                                int out_size) {
    int i = blockIdx.x * blockDim.x + threadIdx.x;
    if (i < out_size) out[i] = X[i % BNN];
}

// ---------------- host orchestration ------------------------------------------
extern "C" void kernel_launch(void* const* d_in, const int* in_sizes, int n_in,
                              void* d_out, int out_size) {
    // input order: cond, x0, sinogram, theta, theta_label, w1,b1,w2,b2,w3,b3,w4,steps
    const float* x0    = (const float*)d_in[1];
    const float* sino  = (const float*)d_in[2];
    const float* theta = (const float*)d_in[3];
    const float* w1    = (const float*)d_in[5];
    const float* b1    = (const float*)d_in[6];
    const float* w2    = (const float*)d_in[7];
    const float* b2    = (const float*)d_in[8];
    const float* w3    = (const float*)d_in[9];
    const float* b3    = (const float*)d_in[10];
    const float* w4    = (const float*)d_in[11];
    const float* steps = (const float*)d_in[12];

    float *X, *Z, *noise, *f0, *f1, *sp, *res, *w2T, *w3T;
    cudaGetSymbolAddress((void**)&X,     g_X);
    cudaGetSymbolAddress((void**)&Z,     g_Z);
    cudaGetSymbolAddress((void**)&noise, g_noise);
    cudaGetSymbolAddress((void**)&f0,    g_f0);
    cudaGetSymbolAddress((void**)&f1,    g_f1);
    cudaGetSymbolAddress((void**)&sp,    g_sp);
    cudaGetSymbolAddress((void**)&res,   g_res);
    cudaGetSymbolAddress((void**)&w2T,   g_w2T);
    cudaGetSymbolAddress((void**)&w3T,   g_w3T);

    const int conv32_smem = (9216 + 32) * 4 + 16 * 10 * 35 * 8;   // 81792 B
    cudaFuncSetAttribute(conv32_kernel,
                         cudaFuncAttributeMaxDynamicSharedMemorySize, conv32_smem);

    const int radon_blocks = (BAD * 32 + 255) / 256;      // warp per output
    const dim3 conv_grid(NN / 32, NN / 8, NB);
    const dim3 filt_grid(NB * NA, 3);

    // one-time weight transpose + X = x0 (independent; both up front)
    wtrans_kernel<<<(NL * 9216 + 255) / 256, 256>>>(w2, w3, w2T, w3T);
    copy_kernel<<<(BNN + 255) / 256, 256>>>(X, x0, BNN);

    for (int n = 0; n < NL; n++) {
        // data-consistency branch
        radon_kernel<<<radon_blocks, 256>>>(X, theta, sp);
        filter_kernel<<<filt_grid, 256>>>(sp, sino, res, /*mode=*/0);
        backproj_kernel<<<(BNN + 255) / 256, 256>>>(res, theta, X, nullptr, Z,
                                                    steps, n, /*mode=*/0);
        // denoiser branch
        conv1_kernel<<<conv_grid, 256>>>(X, w1 + n * 288, b1 + n * 32, f0);
        conv32_kernel<<<conv_grid, 256, conv32_smem>>>(f0, w2T + n * 9216, b2 + n * 32, f1);
        conv32_kernel<<<conv_grid, 256, conv32_smem>>>(f1, w3T + n * 9216, b3 + n * 32, f0);
        conv4_kernel<<<conv_grid, 256>>>(f0, w4 + n * 288, noise);

        radon_kernel<<<radon_blocks, 256>>>(noise, theta, sp);
        filter_kernel<<<filt_grid, 256>>>(sp, nullptr, res, /*mode=*/1);
        backproj_kernel<<<(BNN + 255) / 256, 256>>>(res, theta, Z, noise, X,
                                                    steps, n, /*mode=*/1);
    }

    finalize_kernel<<<(out_size + 255) / 256, 256>>>(X, (float*)d_out, out_size);
}

// round 16
// speedup vs baseline: 1.2930x; 1.0021x over previous
#include <cuda_runtime.h>
#include <math.h>

// Problem constants
#define NN 512          // image size
#define NA 30           // angles
#define ND 729          // detectors
#define NL 3            // layers
#define NB 2            // batch
#define NC 32           // hidden channels

#define PI_F 3.14159265358979323846f

static const int BNN = NB * NN * NN;           // 524288
static const int BAD = NB * NA * ND;           // 43740
static const int NODD = 364;                   // number of odd taps 1..727

typedef unsigned long long ull;

// packed fp32x2 helpers (Blackwell packed-FP32; ptxas never auto-emits these)
#define FMA_F32X2(d, a, b, c) \
    asm("fma.rn.f32x2 %0, %1, %2, %3;" : "=l"(d) : "l"(a), "l"(b), "l"(c))
#define UNPACK_F32X2(lo, hi, in) \
    asm("mov.b64 {%0, %1}, %2;" : "=f"(lo), "=f"(hi) : "l"(in))

// ---------------- scratch (device globals; no allocation allowed) -----------
__device__ float g_X[NB * NN * NN];
__device__ float g_Z[NB * NN * NN];
__device__ float g_noise[NB * NN * NN];
__device__ float g_f0[NB * NC * NN * NN];
__device__ float g_f1[NB * NC * NN * NN];
__device__ float g_sp[NB * NA * ND];
__device__ float g_res[NB * NA * ND];
__device__ float g_w2T[NL * 9216];    // transposed weights: [l][c*9+k][oc]
__device__ float g_w3T[NL * 9216];

// ---------------- trivial copy ----------------------------------------------
__global__ void copy_kernel(float* __restrict__ dst, const float* __restrict__ src, int n) {
    int i = blockIdx.x * blockDim.x + threadIdx.x;
    if (i < n) dst[i] = src[i];
}

// ---------------- weight transpose (one-time, coalesced writes) --------------
// in:  w[l][oc][c][3][3]  ->  out: wT[l][(c*9+k)*32 + oc]
__global__ void wtrans_kernel(const float* __restrict__ w2,
                              const float* __restrict__ w3,
                              float* __restrict__ w2T,
                              float* __restrict__ w3T) {
    int j = blockIdx.x * blockDim.x + threadIdx.x;
    if (j >= NL * 9216) return;
    int l = j / 9216, r = j - l * 9216;
    int ck = r >> 5, oc = r & 31;
    w2T[j] = w2[l * 9216 + oc * 288 + ck];
    w3T[j] = w3[l * 9216 + oc * 288 + ck];
}

// ---------------- Radon forward ----------------------------------------------
__global__ void radon_kernel(const float* __restrict__ img,
                             const float* __restrict__ theta,
                             float* __restrict__ out) {
    int gw   = (int)((blockIdx.x * blockDim.x + threadIdx.x) >> 5);
    int lane = threadIdx.x & 31;
    if (gw >= BAD) return;
    int b   = gw / (NA * ND);
    int rem = gw - b * NA * ND;
    int a   = rem / ND;
    int s   = rem - a * ND;

    float th = theta[a];
    float cs = cosf(th), sn = sinf(th);
    float sv = (float)s - 364.0f;
    float base_r = sv * sn + 255.5f;
    float base_c = sv * cs + 255.5f;
    const float* im = img + b * NN * NN;

    float acc = 0.0f;
    for (int t = lane; t < ND; t += 32) {
        float tv = (float)t - 364.0f;
        float r = base_r + tv * cs;
        float c = base_c - tv * sn;
        float rf = floorf(r), cf = floorf(c);
        int r0 = (int)rf, c0 = (int)cf;
        float wr = r - rf, wc = c - cf;
        float v00 = 0.f, v01 = 0.f, v10 = 0.f, v11 = 0.f;
        bool r0k = (unsigned)r0 < (unsigned)NN;
        bool r1k = (unsigned)(r0 + 1) < (unsigned)NN;
        bool c0k = (unsigned)c0 < (unsigned)NN;
        bool c1k = (unsigned)(c0 + 1) < (unsigned)NN;
        if (r0k) {
            const float* rp = im + r0 * NN;
            if (c0k) v00 = rp[c0];
            if (c1k) v01 = rp[c0 + 1];
        }
        if (r1k) {
            const float* rp = im + (r0 + 1) * NN;
            if (c0k) v10 = rp[c0];
            if (c1k) v11 = rp[c0 + 1];
        }
        acc += (1.f - wr) * ((1.f - wc) * v00 + wc * v01)
             +        wr  * ((1.f - wc) * v10 + wc * v11);
    }
#pragma unroll
    for (int o = 16; o; o >>= 1) acc += __shfl_xor_sync(0xffffffffu, acc, o);
    if (lane == 0) out[gw] = acc;
}

// ---------------- Ramp filter (analytic time-domain equivalent) --------------
__global__ void filter_kernel(const float* __restrict__ sp,
                              const float* __restrict__ sino,
                              float* __restrict__ out, int mode) {
    __shared__ float row[ND];
    __shared__ float coef[NODD];
    int ba = blockIdx.x;                 // b*NA + a
    const float* r = sp + ba * ND;
    for (int i = threadIdx.x; i < ND; i += blockDim.x) row[i] = r[i];
    for (int i = threadIdx.x; i < NODD; i += blockDim.x) {
        float d = 2.0f * (float)i + 1.0f;
        coef[i] = -2.0f / (PI_F * PI_F * d * d);
    }
    __syncthreads();
    const float scale = PI_F / (2.0f * (float)NA);
    int m = blockIdx.y * blockDim.x + threadIdx.x;
    if (m >= ND) return;
    float g = 0.5f * row[m];
    for (int i = 0; i < NODD; i++) {
        int d = 2 * i + 1;
        float sum = 0.f;
        int lo = m - d; if (lo >= 0) sum += row[lo];
        int hi = m + d; if (hi < ND) sum += row[hi];
        g = fmaf(coef[i], sum, g);
    }
    float filtered = g * scale;
    out[ba * ND + m] = (mode == 0) ? (sino[ba * ND + m] - filtered) : filtered;
}

// ---------------- Backprojection (fused epilogue) -----------------------------
__global__ void backproj_kernel(const float* __restrict__ sino,
                                const float* __restrict__ theta,
                                const float* __restrict__ base,
                                const float* __restrict__ addl,
                                float* __restrict__ out,
                                const float* __restrict__ steps, int layer,
                                int mode) {
    __shared__ float cs_s[NA], sn_s[NA];
    if (threadIdx.x < NA) {
        float th = theta[threadIdx.x];
        cs_s[threadIdx.x] = cosf(th);
        sn_s[threadIdx.x] = sinf(th);
    }
    __syncthreads();
    int p = blockIdx.x * blockDim.x + threadIdx.x;
    if (p >= BNN) return;
    int b  = p / (NN * NN);
    int ij = p - b * NN * NN;
    int i  = ij / NN, j = ij - i * NN;
    float xi = (float)i - 255.5f;
    float xj = (float)j - 255.5f;
    const float* srow = sino + b * NA * ND;
    float acc = 0.0f;
#pragma unroll 5
    for (int a = 0; a < NA; a++) {
        float idx = cs_s[a] * xj + sn_s[a] * xi + 364.0f;
        float lof = floorf(idx);
        int lo = (int)lof;
        float w = idx - lof;
        float v = 0.f;
        if ((unsigned)lo < (unsigned)ND)       v += srow[a * ND + lo] * (1.0f - w);
        if ((unsigned)(lo + 1) < (unsigned)ND) v += srow[a * ND + lo + 1] * w;
        acc += v;
    }
    float step = steps[layer];
    float r;
    if (mode == 0) r = base[p] + step * acc;
    else           r = base[p] + addl[p] - step * acc;
    out[p] = r;
}

// ---------------- Conv 1 -> 32, ReLU -----------------------------------------
__global__ void conv1_kernel(const float* __restrict__ in,   // [B,N,N]
                             const float* __restrict__ w,    // [32,1,3,3]
                             const float* __restrict__ bias, // [32]
                             float* __restrict__ out) {      // [B,32,N,N]
    __shared__ float ws[32 * 9];
    __shared__ float bs[32];
    __shared__ float tile[10][35];
    int tid = threadIdx.x;
    for (int i = tid; i < 288; i += 256) ws[i] = w[i];
    if (tid < 32)  bs[tid] = bias[tid];
    int tx0 = blockIdx.x * 32, ty0 = blockIdx.y * 8, b = blockIdx.z;
    const float* ip = in + b * NN * NN;
    for (int i = tid; i < 340; i += 256) {
        int r = i / 34, c = i % 34;
        int gy = ty0 + r - 1, gx = tx0 + c - 1;
        tile[r][c] = ((unsigned)gy < (unsigned)NN && (unsigned)gx < (unsigned)NN)
                         ? ip[gy * NN + gx] : 0.f;
    }
    __syncthreads();
    int lx = tid & 31, ly = tid >> 5;
    float p[9];
#pragma unroll
    for (int ky = 0; ky < 3; ky++)
#pragma unroll
        for (int kx = 0; kx < 3; kx++) p[ky * 3 + kx] = tile[ly + ky][lx + kx];
    int gy = ty0 + ly, gx = tx0 + lx;
#pragma unroll
    for (int oc = 0; oc < 32; oc++) {
        float acc = bs[oc];
#pragma unroll
        for (int k = 0; k < 9; k++) acc = fmaf(ws[oc * 9 + k], p[k], acc);
        acc = fmaxf(acc, 0.f);
        out[((b * NC + oc) * NN + gy) * NN + gx] = acc;
    }
}

// ---------------- Conv 32 -> 32, ReLU ----------------------------------------
// f32x2 over ADJACENT OUTPUT CHANNELS, zero pack/unpack in the mainloop:
//  - weights pre-transposed to [ck][oc] (coalesced smem fill); oc-pair = LDS.64
//  - input tiles duplicated in smem as {v,v}: pre-broadcast pair per LDS.64
//  - 16-channel phases: smem = 36864 + 128 + 44800 = 81792 B -> 2 blocks/SM
// 256 threads; warp w: oc-group (w&3)*8, row-half (w>>2)*4.
// lane: ly = half*4 + (lane&3), lx0 = (lane>>2)*4; per thread 4 px x 4 oc-pairs.
__global__ void __launch_bounds__(256, 2)
conv32_kernel(const float* __restrict__ in,   // [B,32,N,N]
              const float* __restrict__ wT,   // [288][32] pre-transposed
              const float* __restrict__ bias, // [32]
              float* __restrict__ out) {      // [B,32,N,N]
    extern __shared__ float sm[];
    float* ws = sm;                            // 9216 floats [ck*32 + oc]
    float* bs = sm + 9216;                     // 32
    ull*   td = (ull*)(sm + 9216 + 32);        // 16*10*35 dup-pairs (44800 B)
    int tid = threadIdx.x;

    for (int i = tid; i < 9216; i += 256) ws[i] = wT[i];   // coalesced
    if (tid < 32) bs[tid] = bias[tid];

    int tx0 = blockIdx.x * 32, ty0 = blockIdx.y * 8, b = blockIdx.z;
    const float* inb = in + b * NC * NN * NN;

    int warp = tid >> 5, lane = tid & 31;
    int ocg  = warp & 3;               // oc base = ocg*8 (4 pairs)
    int half = warp >> 2;              // 0/1 -> rows 0-3 / 4-7
    int ly   = half * 4 + (lane & 3);
    int lx0  = (lane >> 2) * 4;        // 4 consecutive px

    ull acc[4][4];                     // [oc-pair][px]
#pragma unroll
    for (int o = 0; o < 4; o++)
#pragma unroll
        for (int q = 0; q < 4; q++) acc[o][q] = 0ULL;

    const ull* wpb = (const ull*)ws;   // pair index = ck*16 + ocp
    int ocp0 = ocg * 4;

#pragma unroll 1
    for (int ph = 0; ph < 2; ph++) {
        __syncthreads();
        // load 16 duplicated halo tiles for channels ph*16 .. ph*16+15
        for (int i = tid; i < 16 * 340; i += 256) {
            int c   = i / 340;
            int rem = i - c * 340;
            int r   = rem / 34;
            int cc  = rem - r * 34;
            int gy = ty0 + r - 1, gx = tx0 + cc - 1;
            float v = ((unsigned)gy < (unsigned)NN && (unsigned)gx < (unsigned)NN)
                          ? inb[(ph * 16 + c) * NN * NN + gy * NN + gx] : 0.f;
            ((float2*)td)[(c * 10 + r) * 35 + cc] = make_float2(v, v);
        }
        __syncthreads();

#pragma unroll 1
        for (int c = 0; c < 16; c++) {
            const ull* tl = td + (c * 10) * 35;
            const ull* wc = wpb + (ph * 16 + c) * 144 + ocp0;   // + k*16 + o
#pragma unroll
            for (int ky = 0; ky < 3; ky++) {
                const ull* rp = tl + (ly + ky) * 35 + lx0;
                ull v[6];
#pragma unroll
                for (int k = 0; k < 6; k++) v[k] = rp[k];
#pragma unroll
                for (int kx = 0; kx < 3; kx++) {
                    const ull* wk = wc + (ky * 3 + kx) * 16;
#pragma unroll
                    for (int o = 0; o < 4; o++) {
                        ull wp = wk[o];           // warp-uniform broadcast
                        FMA_F32X2(acc[o][0], wp, v[kx + 0], acc[o][0]);
                        FMA_F32X2(acc[o][1], wp, v[kx + 1], acc[o][1]);
                        FMA_F32X2(acc[o][2], wp, v[kx + 2], acc[o][2]);
                        FMA_F32X2(acc[o][3], wp, v[kx + 3], acc[o][3]);
                    }
                }
            }
        }
    }

    int gy = ty0 + ly;
#pragma unroll
    for (int o = 0; o < 4; o++) {
        int oc = ocg * 8 + 2 * o;
        float b0 = bs[oc], b1 = bs[oc + 1];
        float lo0, hi0, lo1, hi1, lo2, hi2, lo3, hi3;
        UNPACK_F32X2(lo0, hi0, acc[o][0]);
        UNPACK_F32X2(lo1, hi1, acc[o][1]);
        UNPACK_F32X2(lo2, hi2, acc[o][2]);
        UNPACK_F32X2(lo3, hi3, acc[o][3]);
        float4 r0 = make_float4(fmaxf(lo0 + b0, 0.f), fmaxf(lo1 + b0, 0.f),
                                fmaxf(lo2 + b0, 0.f), fmaxf(lo3 + b0, 0.f));
        float4 r1 = make_float4(fmaxf(hi0 + b1, 0.f), fmaxf(hi1 + b1, 0.f),
                                fmaxf(hi2 + b1, 0.f), fmaxf(hi3 + b1, 0.f));
        *(float4*)(out + ((b * NC + oc)     * NN + gy) * NN + tx0 + lx0) = r0;
        *(float4*)(out + ((b * NC + oc + 1) * NN + gy) * NN + tx0 + lx0) = r1;
    }
}

// ---------------- Conv 32 -> 1 (all channels resident, single sync) ----------
__global__ void conv4_kernel(const float* __restrict__ in,  // [B,32,N,N]
                             const float* __restrict__ w,   // [1,32,3,3]
                             float* __restrict__ out) {     // [B,N,N]
    __shared__ float ws[288];
    __shared__ float tiles[32 * 350];
    int tid = threadIdx.x;
    for (int i = tid; i < 288; i += 256) ws[i] = w[i];
    int tx0 = blockIdx.x * 32, ty0 = blockIdx.y * 8, b = blockIdx.z;
    const float* inb = in + b * NC * NN * NN;
    for (int i = tid; i < 32 * 340; i += 256) {
        int c   = i / 340;
        int rem = i - c * 340;
        int r   = rem / 34;
        int cc  = rem - r * 34;
        int gy = ty0 + r - 1, gx = tx0 + cc - 1;
        tiles[c * 350 + r * 35 + cc] =
            ((unsigned)gy < (unsigned)NN && (unsigned)gx < (unsigned)NN)
                ? inb[c * NN * NN + gy * NN + gx] : 0.f;
    }
    __syncthreads();
    int lx = tid & 31, ly = tid >> 5;
    float acc = 0.f;
    for (int c = 0; c < NC; c++) {
        const float* tl = tiles + c * 350;
#pragma unroll
        for (int ky = 0; ky < 3; ky++)
#pragma unroll
            for (int kx = 0; kx < 3; kx++)
                acc = fmaf(ws[c * 9 + ky * 3 + kx], tl[(ly + ky) * 35 + lx + kx], acc);
    }
    out[b * NN * NN + (ty0 + ly) * NN + tx0 + lx] = acc;
}

// ---------------- finalize: 3 copies of X -------------------------------------
__global__ void finalize_kernel(const float* __restrict__ X, float* __restrict__ out,
                                int out_size) {
    int i = blockIdx.x * blockDim.x + threadIdx.x;
    if (i < out_size) out[i] = X[i % BNN];
}

// ---------------- host orchestration ------------------------------------------
extern "C" void kernel_launch(void* const* d_in, const int* in_sizes, int n_in,
                              void* d_out, int out_size) {
    // input order: cond, x0, sinogram, theta, theta_label, w1,b1,w2,b2,w3,b3,w4,steps
    const float* x0    = (const float*)d_in[1];
    const float* sino  = (const float*)d_in[2];
    const float* theta = (const float*)d_in[3];
    const float* w1    = (const float*)d_in[5];
    const float* b1    = (const float*)d_in[6];
    const float* w2    = (const float*)d_in[7];
    const float* b2    = (const float*)d_in[8];
    const float* w3    = (const float*)d_in[9];
    const float* b3    = (const float*)d_in[10];
    const float* w4    = (const float*)d_in[11];
    const float* steps = (const float*)d_in[12];

    float *X, *Z, *noise, *f0, *f1, *sp, *res, *w2T, *w3T;
    cudaGetSymbolAddress((void**)&X,     g_X);
    cudaGetSymbolAddress((void**)&Z,     g_Z);
    cudaGetSymbolAddress((void**)&noise, g_noise);
    cudaGetSymbolAddress((void**)&f0,    g_f0);
    cudaGetSymbolAddress((void**)&f1,    g_f1);
    cudaGetSymbolAddress((void**)&sp,    g_sp);
    cudaGetSymbolAddress((void**)&res,   g_res);
    cudaGetSymbolAddress((void**)&w2T,   g_w2T);
    cudaGetSymbolAddress((void**)&w3T,   g_w3T);

    const int conv32_smem = (9216 + 32) * 4 + 16 * 10 * 35 * 8;   // 81792 B
    cudaFuncSetAttribute(conv32_kernel,
                         cudaFuncAttributeMaxDynamicSharedMemorySize, conv32_smem);

    const int radon_blocks = (BAD * 32 + 255) / 256;      // warp per output
    const dim3 conv_grid(NN / 32, NN / 8, NB);
    const dim3 filt_grid(NB * NA, 3);

    // one-time weight transpose + X = x0 (independent; both up front)
    wtrans_kernel<<<(NL * 9216 + 255) / 256, 256>>>(w2, w3, w2T, w3T);
    copy_kernel<<<(BNN + 255) / 256, 256>>>(X, x0, BNN);

    for (int n = 0; n < NL; n++) {
        // data-consistency branch
        radon_kernel<<<radon_blocks, 256>>>(X, theta, sp);
        filter_kernel<<<filt_grid, 256>>>(sp, sino, res, /*mode=*/0);
        backproj_kernel<<<(BNN + 255) / 256, 256>>>(res, theta, X, nullptr, Z,
                                                    steps, n, /*mode=*/0);
        // denoiser branch
        conv1_kernel<<<conv_grid, 256>>>(X, w1 + n * 288, b1 + n * 32, f0);
        conv32_kernel<<<conv_grid, 256, conv32_smem>>>(f0, w2T + n * 9216, b2 + n * 32, f1);
        conv32_kernel<<<conv_grid, 256, conv32_smem>>>(f1, w3T + n * 9216, b3 + n * 32, f0);
        conv4_kernel<<<conv_grid, 256>>>(f0, w4 + n * 288, noise);

        radon_kernel<<<radon_blocks, 256>>>(noise, theta, sp);
        filter_kernel<<<filt_grid, 256>>>(sp, nullptr, res, /*mode=*/1);
        backproj_kernel<<<(BNN + 255) / 256, 256>>>(res, theta, Z, noise, X,
                                                    steps, n, /*mode=*/1);
    }

    finalize_kernel<<<(out_size + 255) / 256, 256>>>(X, (float*)d_out, out_size);
}